// round 15
// baseline (speedup 1.0000x reference)
#include <cuda_runtime.h>
#include <cstdint>
#include <mma.h>
using namespace nvcuda;

#define N_NODES 100000
#define N_PAD   100096   // 782*128, for unguarded wmma stores
#define NE      1600000
#define FIN     1433
#define HD      64
#define NH      2
#define NC      7
#define OC      14   // NH*NC
#define SCAN_T  1024
#define SCAN_B  ((N_NODES + SCAN_T - 1) / SCAN_T)   // 98

// ---------------- scratch (static device globals; no allocation) ----------------
__device__ float g_dinv[N_NODES];
__device__ __align__(16) float g_bufA[N_PAD   * HD];
__device__ __align__(16) float g_bufB[N_NODES * HD];
__device__ float g_hg  [N_NODES * OC];
__device__ float g_as  [N_NODES * NH];
__device__ float g_ad  [N_NODES * NH];
// CSR (incoming edges per node)
__device__ int   g_cnt [N_NODES];
__device__ int   g_ptr [N_NODES + 1];
__device__ int   g_cur [N_NODES];
__device__ int   g_csrc[NE];
__device__ int   g_bsum[SCAN_B + 1];

// ---------------- helpers ----------------
__device__ __forceinline__ float lrelu(float x) { return x > 0.f ? x : 0.2f * x; }

__device__ __forceinline__ void cp_async4(void* smem, const void* gmem, bool pred) {
    unsigned int s = (unsigned int)__cvta_generic_to_shared(smem);
    int sz = pred ? 4 : 0;
    asm volatile("cp.async.ca.shared.global [%0], [%1], 4, %2;" :: "r"(s), "l"(gmem), "r"(sz));
}
__device__ __forceinline__ void cp_async16(void* smem, const void* gmem, bool pred) {
    unsigned int s = (unsigned int)__cvta_generic_to_shared(smem);
    int sz = pred ? 16 : 0;
    asm volatile("cp.async.cg.shared.global [%0], [%1], 16, %2;" :: "r"(s), "l"(gmem), "r"(sz));
}

// ---------------- CSR build ----------------
__global__ void k_zero_cnt() {
    int i = blockIdx.x * blockDim.x + threadIdx.x;
    if (i < N_NODES) g_cnt[i] = 0;
}
__global__ void k_count(const int* __restrict__ dst) {
    int e = blockIdx.x * blockDim.x + threadIdx.x;
    if (e < NE) atomicAdd(&g_cnt[dst[e]], 1);
}
__global__ void k_dinv() {
    int i = blockIdx.x * blockDim.x + threadIdx.x;
    if (i < N_NODES) g_dinv[i] = rsqrtf((float)(g_cnt[i] + 1));  // +1 self-loop
}
// block-level exclusive scan of g_cnt -> g_ptr (partial), block totals -> g_bsum
__global__ void __launch_bounds__(SCAN_T) k_scan1() {
    __shared__ int wsum[32];
    int t = threadIdx.x, lane = t & 31, warp = t >> 5;
    int i = blockIdx.x * SCAN_T + t;
    int v = (i < N_NODES) ? g_cnt[i] : 0;
    int x = v;
#pragma unroll
    for (int off = 1; off < 32; off <<= 1) {
        int y = __shfl_up_sync(0xffffffffu, x, off);
        if (lane >= off) x += y;
    }
    if (lane == 31) wsum[warp] = x;
    __syncthreads();
    if (warp == 0) {
        int z = wsum[lane];
#pragma unroll
        for (int off = 1; off < 32; off <<= 1) {
            int y = __shfl_up_sync(0xffffffffu, z, off);
            if (lane >= off) z += y;
        }
        wsum[lane] = z;
    }
    __syncthreads();
    int excl = x - v + (warp ? wsum[warp - 1] : 0);
    if (i < N_NODES) g_ptr[i] = excl;
    if (t == 0) g_bsum[blockIdx.x] = wsum[31];
}
__global__ void k_scan2() {
    if (threadIdx.x == 0) {
        int run = 0;
        for (int b = 0; b < SCAN_B; b++) { int t = g_bsum[b]; g_bsum[b] = run; run += t; }
    }
}
__global__ void k_scan3() {
    int i = blockIdx.x * blockDim.x + threadIdx.x;
    if (i < N_NODES) {
        int p = g_ptr[i] + g_bsum[i / SCAN_T];
        g_ptr[i] = p;
        g_cur[i] = p;
    }
    if (i == 0) g_ptr[N_NODES] = NE;
}
__global__ void k_fill(const int* __restrict__ src, const int* __restrict__ dst) {
    int e = blockIdx.x * blockDim.x + threadIdx.x;
    if (e >= NE) return;
    int d = dst[e];
    int p = atomicAdd(&g_cur[d], 1);
    g_csrc[p] = src[e];
}

// ---------------- GEMM1 (TF32 tensor cores, 3-stage cp.async): g_bufA = x @ W1 ----------------
#define KT_TILES ((FIN + 15) / 16)   // 90
__global__ void __launch_bounds__(256) k_gemm1(const float* __restrict__ X,
                                               const float* __restrict__ W) {
    __shared__ __align__(16) float As[3][16][136];   // [stage][k][m]
    __shared__ __align__(16) float Bs[3][16][72];    // [stage][k][n]
    const int t    = threadIdx.x;
    const int warp = t >> 5;
    const int wm   = warp >> 1;
    const int wn   = warp & 1;
    const int block_row = blockIdx.x * 128;

    wmma::fragment<wmma::accumulator, 16, 16, 8, float> acc[2][2];
#pragma unroll
    for (int i = 0; i < 2; i++)
#pragma unroll
        for (int j = 0; j < 2; j++) wmma::fill_fragment(acc[i][j], 0.0f);

    const int ar = t >> 4;
    const int ak = t & 15;
    const int brow = t >> 4;
    const int bc4  = t & 15;

#pragma unroll
    for (int pt = 0; pt < 2; pt++) {
        const int k0 = pt * 16;
#pragma unroll
        for (int i = 0; i < 8; i++) {
            int r = ar + i * 16;
            int gr = block_row + r;
            cp_async4(&As[pt][ak][r], X + (size_t)gr * FIN + k0 + ak, gr < N_NODES);
        }
        cp_async16(&Bs[pt][brow][bc4 * 4], W + (k0 + brow) * HD + bc4 * 4, true);
        asm volatile("cp.async.commit_group;");
    }

    for (int kt = 0; kt < KT_TILES; kt++) {
        const int cur = kt % 3;
        if (kt + 2 < KT_TILES) {
            const int nk0 = (kt + 2) * 16;
            const int nxt = (kt + 2) % 3;
#pragma unroll
            for (int i = 0; i < 8; i++) {
                int r = ar + i * 16;
                int gr = block_row + r, gk = nk0 + ak;
                cp_async4(&As[nxt][ak][r], X + (size_t)gr * FIN + gk,
                          (gr < N_NODES) && (gk < FIN));
            }
            {
                int gk = nk0 + brow;
                cp_async16(&Bs[nxt][brow][bc4 * 4], W + gk * HD + bc4 * 4, gk < FIN);
            }
            asm volatile("cp.async.commit_group;");
            asm volatile("cp.async.wait_group 2;");
        } else {
            asm volatile("cp.async.wait_group 0;");
        }
        __syncthreads();

#pragma unroll
        for (int ks = 0; ks < 2; ks++) {
            wmma::fragment<wmma::matrix_a, 16, 16, 8, wmma::precision::tf32, wmma::col_major> af[2];
            wmma::fragment<wmma::matrix_b, 16, 16, 8, wmma::precision::tf32, wmma::row_major> bf[2];
#pragma unroll
            for (int i = 0; i < 2; i++)
                wmma::load_matrix_sync(af[i], &As[cur][ks * 8][wm * 32 + i * 16], 136);
#pragma unroll
            for (int j = 0; j < 2; j++)
                wmma::load_matrix_sync(bf[j], &Bs[cur][ks * 8][wn * 32 + j * 16], 72);
#pragma unroll
            for (int i = 0; i < 2; i++)
#pragma unroll
                for (int j = 0; j < 2; j++)
                    wmma::mma_sync(acc[i][j], af[i], bf[j], acc[i][j]);
        }
        __syncthreads();
    }

#pragma unroll
    for (int i = 0; i < 2; i++) {
        int row = block_row + wm * 32 + i * 16;
#pragma unroll
        for (int j = 0; j < 2; j++) {
            int col = wn * 32 + j * 16;
            wmma::store_matrix_sync(&g_bufA[row * HD + col], acc[i][j], HD, wmma::mem_row_major);
        }
    }
}

// ---------------- GCN propagation as gather: bufB[i] = sum over incoming edges ----------------
// warp per node; lane owns one float2 of the 64-float row.
__global__ void __launch_bounds__(256) k_gather() {
    int w = (blockIdx.x * blockDim.x + threadIdx.x) >> 5;
    int lane = threadIdx.x & 31;
    if (w >= N_NODES) return;
    float di = g_dinv[w];
    const float2* __restrict__ inp = (const float2*)g_bufA;
    float2 a = inp[w * 32 + lane];
    float s2 = di * di;
    float2 acc = make_float2(a.x * s2, a.y * s2);   // self-loop
    int idx = g_ptr[w], end = g_ptr[w + 1];
    int sN = (idx < end) ? g_csrc[idx] : 0;
    while (idx < end) {
        int s = sN;
        if (idx + 1 < end) sN = g_csrc[idx + 1];
        float nrm = g_dinv[s] * di;
        float2 v = inp[s * 32 + lane];
        acc.x += v.x * nrm;
        acc.y += v.y * nrm;
        idx++;
    }
    ((float2*)g_bufB)[w * 32 + lane] = acc;
}

// ---------------- GEMM2: bufA = relu(bufB + b1) @ W2   (64x64) ----------------
__global__ void __launch_bounds__(256) k_gemm2(const float* __restrict__ bias,
                                               const float* __restrict__ W) {
    __shared__ float Ws[HD * HD];
    __shared__ float As2[16][HD];
    const int t = threadIdx.x;
    const int rows = blockIdx.x * 16;
#pragma unroll
    for (int i = 0; i < 16; i++) Ws[t + i * 256] = W[t + i * 256];
#pragma unroll
    for (int i = 0; i < 4; i++) {
        int idx = t + i * 256;
        int r = idx >> 6, c = idx & 63;
        int gr = rows + r;
        float v = 0.f;
        if (gr < N_NODES) v = fmaxf(g_bufB[gr * HD + c] + bias[c], 0.f);
        As2[r][c] = v;
    }
    __syncthreads();
    int r = t >> 4, cg = t & 15;
    float acc[4] = {0.f, 0.f, 0.f, 0.f};
#pragma unroll
    for (int k = 0; k < HD; k++) {
        float a = As2[r][k];
#pragma unroll
        for (int j = 0; j < 4; j++) acc[j] += a * Ws[k * HD + cg + 16 * j];
    }
    int gr = rows + r;
    if (gr < N_NODES) {
#pragma unroll
        for (int j = 0; j < 4; j++) g_bufA[gr * HD + cg + 16 * j] = acc[j];
    }
}

// ---------------- GAT transform: hg = relu(bufB + b2) @ Wg  (64x14) ----------------
__global__ void k_gat_transform(const float* __restrict__ bias, const float* __restrict__ Wg) {
    __shared__ float Ws[HD * OC];
    int t = threadIdx.x;
    for (int idx = t; idx < HD * OC; idx += blockDim.x) Ws[idx] = Wg[idx];
    __syncthreads();
    int node = (blockIdx.x * blockDim.x + t) >> 5;
    int lane = t & 31;
    if (node >= N_NODES) return;
    float f_lo = fmaxf(g_bufB[node * HD + lane]      + bias[lane],      0.f);
    float f_hi = fmaxf(g_bufB[node * HD + 32 + lane] + bias[32 + lane], 0.f);
    int c = lane < OC ? lane : 0;
    float acc = 0.f;
#pragma unroll
    for (int k = 0; k < 32; k++) {
        float a = __shfl_sync(0xffffffffu, f_lo, k);
        acc += a * Ws[k * OC + c];
    }
#pragma unroll
    for (int k = 0; k < 32; k++) {
        float a = __shfl_sync(0xffffffffu, f_hi, k);
        acc += a * Ws[(k + 32) * OC + c];
    }
    if (lane < OC) g_hg[node * OC + lane] = acc;
}

// ---------------- attention scalars ----------------
__global__ void k_node_att(const float* __restrict__ att_src, const float* __restrict__ att_dst) {
    int tid = blockIdx.x * blockDim.x + threadIdx.x;
    if (tid >= N_NODES * NH) return;
    int i = tid >> 1, h = tid & 1;
    const float* hrow = g_hg + i * OC + h * NC;
    float as = 0.f, ad = 0.f;
#pragma unroll
    for (int c = 0; c < NC; c++) {
        as += hrow[c] * att_src[h * NC + c];
        ad += hrow[c] * att_dst[h * NC + c];
    }
    g_as[tid] = as;
    g_ad[tid] = ad;
}

// ---------------- fused GAT gather: segment max + softmax + aggregate + log_softmax ----------
// warp per node; lanes stride over incoming edges.
__global__ void __launch_bounds__(256) k_gat_gather(const float* __restrict__ bg,
                                                    float* __restrict__ out) {
    int w = (blockIdx.x * blockDim.x + threadIdx.x) >> 5;
    int lane = threadIdx.x & 31;
    if (w >= N_NODES) return;
    const int beg = g_ptr[w], end = g_ptr[w + 1];
    const float ad0 = g_ad[w * 2], ad1 = g_ad[w * 2 + 1];
    const float es0 = lrelu(g_as[w * 2]     + ad0);   // self-loop e-values
    const float es1 = lrelu(g_as[w * 2 + 1] + ad1);

    // pass 1: segment max (self seeds every lane)
    float m0 = es0, m1 = es1;
    for (int idx = beg + lane; idx < end; idx += 32) {
        int s = g_csrc[idx];
        m0 = fmaxf(m0, lrelu(g_as[s * 2]     + ad0));
        m1 = fmaxf(m1, lrelu(g_as[s * 2 + 1] + ad1));
    }
#pragma unroll
    for (int off = 16; off > 0; off >>= 1) {
        m0 = fmaxf(m0, __shfl_xor_sync(0xffffffffu, m0, off));
        m1 = fmaxf(m1, __shfl_xor_sync(0xffffffffu, m1, off));
    }

    // pass 2: denominator + weighted feature accumulation
    float s0 = 0.f, s1 = 0.f;
    float num[OC];
#pragma unroll
    for (int c = 0; c < OC; c++) num[c] = 0.f;
    if (lane == 0) {   // self-loop contribution once
        float p0 = expf(es0 - m0), p1 = expf(es1 - m1);
        s0 = p0; s1 = p1;
        const float* hr = g_hg + w * OC;
#pragma unroll
        for (int c = 0; c < NC; c++)  num[c]      = p0 * hr[c];
#pragma unroll
        for (int c = 0; c < NC; c++)  num[NC + c] = p1 * hr[NC + c];
    }
    for (int idx = beg + lane; idx < end; idx += 32) {
        int s = g_csrc[idx];
        float p0 = expf(lrelu(g_as[s * 2]     + ad0) - m0);
        float p1 = expf(lrelu(g_as[s * 2 + 1] + ad1) - m1);
        s0 += p0; s1 += p1;
        const float* hr = g_hg + s * OC;
#pragma unroll
        for (int c = 0; c < NC; c++)  num[c]      += p0 * hr[c];
#pragma unroll
        for (int c = 0; c < NC; c++)  num[NC + c] += p1 * hr[NC + c];
    }
#pragma unroll
    for (int off = 16; off > 0; off >>= 1) {
        s0 += __shfl_xor_sync(0xffffffffu, s0, off);
        s1 += __shfl_xor_sync(0xffffffffu, s1, off);
#pragma unroll
        for (int c = 0; c < OC; c++)
            num[c] += __shfl_xor_sync(0xffffffffu, num[c], off);
    }

    // logits held one-per-lane (lanes 0..13), then warp log_softmax
    float v = -1e30f;
    if (lane < OC) {
        float denom = (lane < NC ? s0 : s1) + 1e-16f;
        v = num[lane] / denom + bg[lane];
    }
    float mx = v;
#pragma unroll
    for (int off = 16; off > 0; off >>= 1)
        mx = fmaxf(mx, __shfl_xor_sync(0xffffffffu, mx, off));
    float ex = (lane < OC) ? expf(v - mx) : 0.f;
    float se = ex;
#pragma unroll
    for (int off = 16; off > 0; off >>= 1)
        se += __shfl_xor_sync(0xffffffffu, se, off);
    float lse = mx + logf(se);
    if (lane < OC) out[w * OC + lane] = v - lse;
}

// ---------------- launch ----------------
extern "C" void kernel_launch(void* const* d_in, const int* in_sizes, int n_in,
                              void* d_out, int out_size) {
    const float* x       = (const float*)d_in[0];
    const int*   ei      = (const int*)  d_in[1];
    const float* W1      = (const float*)d_in[2];
    const float* b1      = (const float*)d_in[3];
    const float* W2      = (const float*)d_in[4];
    const float* b2      = (const float*)d_in[5];
    const float* Wg      = (const float*)d_in[6];
    const float* att_src = (const float*)d_in[7];
    const float* att_dst = (const float*)d_in[8];
    const float* bg      = (const float*)d_in[9];
    float* out = (float*)d_out;

    const int* src = ei;
    const int* dst = ei + NE;

    const int T = 256;
    // CSR build + normalization
    k_zero_cnt<<<(N_NODES + T - 1) / T, T>>>();
    k_count<<<(NE + T - 1) / T, T>>>(dst);
    k_dinv<<<(N_NODES + T - 1) / T, T>>>();
    k_scan1<<<SCAN_B, SCAN_T>>>();
    k_scan2<<<1, 32>>>();
    k_scan3<<<(N_NODES + T - 1) / T, T>>>();
    k_fill<<<(NE + T - 1) / T, T>>>(src, dst);

    // layer 1: transform (tensor cores + cp.async), gather
    k_gemm1<<<(N_NODES + 127) / 128, 256>>>(x, W1);
    k_gather<<<(N_NODES * 32 + T - 1) / T, T>>>();

    // layer 2: relu(agg+b1) @ W2, gather
    k_gemm2<<<(N_NODES + 15) / 16, 256>>>(b1, W2);
    k_gather<<<(N_NODES * 32 + T - 1) / T, T>>>();

    // GAT head (fused)
    k_gat_transform<<<(N_NODES * 32 + T - 1) / T, T>>>(b2, Wg);
    k_node_att<<<(N_NODES * NH + T - 1) / T, T>>>(att_src, att_dst);
    k_gat_gather<<<(N_NODES * 32 + T - 1) / T, T>>>(bg, out);
}

// round 16
// speedup vs baseline: 1.4851x; 1.4851x over previous
#include <cuda_runtime.h>
#include <cstdint>
#include <mma.h>
using namespace nvcuda;

#define N_NODES 100000
#define N_PAD   100096   // 782*128, for unguarded wmma stores
#define NE      1600000
#define FIN     1433
#define HD      64
#define NH      2
#define NC      7
#define OC      14   // NH*NC
#define SCAN_T  1024
#define SCAN_B  ((N_NODES + SCAN_T - 1) / SCAN_T)   // 98

// ---------------- scratch (static device globals; no allocation) ----------------
__device__ float g_dinv[N_NODES];
__device__ __align__(16) float g_bufA[N_PAD   * HD];
__device__ __align__(16) float g_bufB[N_NODES * HD];
__device__ float g_hg  [N_NODES * OC];
__device__ float g_as  [N_NODES * NH];
__device__ float g_ad  [N_NODES * NH];
// CSR (incoming edges per node)
__device__ int   g_cnt [N_NODES];
__device__ int   g_ptr [N_NODES + 1];
__device__ int   g_cur [N_NODES];
__device__ int   g_csrc[NE];
__device__ int   g_bsum[SCAN_B + 1];

// ---------------- helpers ----------------
__device__ __forceinline__ float lrelu(float x) { return x > 0.f ? x : 0.2f * x; }

__device__ __forceinline__ void cp_async4(void* smem, const void* gmem, bool pred) {
    unsigned int s = (unsigned int)__cvta_generic_to_shared(smem);
    int sz = pred ? 4 : 0;
    asm volatile("cp.async.ca.shared.global [%0], [%1], 4, %2;" :: "r"(s), "l"(gmem), "r"(sz));
}
__device__ __forceinline__ void cp_async16(void* smem, const void* gmem, bool pred) {
    unsigned int s = (unsigned int)__cvta_generic_to_shared(smem);
    int sz = pred ? 16 : 0;
    asm volatile("cp.async.cg.shared.global [%0], [%1], 16, %2;" :: "r"(s), "l"(gmem), "r"(sz));
}

// ---------------- CSR build ----------------
__global__ void k_zero_cnt() {
    int i = blockIdx.x * blockDim.x + threadIdx.x;
    if (i < N_NODES) g_cnt[i] = 0;
}
__global__ void k_count(const int* __restrict__ dst) {
    int e = blockIdx.x * blockDim.x + threadIdx.x;
    if (e < NE) atomicAdd(&g_cnt[dst[e]], 1);
}
__global__ void k_dinv() {
    int i = blockIdx.x * blockDim.x + threadIdx.x;
    if (i < N_NODES) g_dinv[i] = rsqrtf((float)(g_cnt[i] + 1));  // +1 self-loop
}
// block-level exclusive scan of g_cnt -> g_ptr (partial), block totals -> g_bsum
__global__ void __launch_bounds__(SCAN_T) k_scan1() {
    __shared__ int wsum[32];
    int t = threadIdx.x, lane = t & 31, warp = t >> 5;
    int i = blockIdx.x * SCAN_T + t;
    int v = (i < N_NODES) ? g_cnt[i] : 0;
    int x = v;
#pragma unroll
    for (int off = 1; off < 32; off <<= 1) {
        int y = __shfl_up_sync(0xffffffffu, x, off);
        if (lane >= off) x += y;
    }
    if (lane == 31) wsum[warp] = x;
    __syncthreads();
    if (warp == 0) {
        int z = wsum[lane];
#pragma unroll
        for (int off = 1; off < 32; off <<= 1) {
            int y = __shfl_up_sync(0xffffffffu, z, off);
            if (lane >= off) z += y;
        }
        wsum[lane] = z;
    }
    __syncthreads();
    int excl = x - v + (warp ? wsum[warp - 1] : 0);
    if (i < N_NODES) g_ptr[i] = excl;
    if (t == 0) g_bsum[blockIdx.x] = wsum[31];
}
__global__ void k_scan2() {
    if (threadIdx.x == 0) {
        int run = 0;
        for (int b = 0; b < SCAN_B; b++) { int t = g_bsum[b]; g_bsum[b] = run; run += t; }
    }
}
__global__ void k_scan3() {
    int i = blockIdx.x * blockDim.x + threadIdx.x;
    if (i < N_NODES) {
        int p = g_ptr[i] + g_bsum[i / SCAN_T];
        g_ptr[i] = p;
        g_cur[i] = p;
    }
    if (i == 0) g_ptr[N_NODES] = NE;
}
__global__ void k_fill(const int* __restrict__ src, const int* __restrict__ dst) {
    int e = blockIdx.x * blockDim.x + threadIdx.x;
    if (e >= NE) return;
    int d = dst[e];
    int p = atomicAdd(&g_cur[d], 1);
    g_csrc[p] = src[e];
}

// ---------------- GEMM1 (TF32 tensor cores, 3-stage cp.async): g_bufA = x @ W1 ----------------
#define KT_TILES ((FIN + 15) / 16)   // 90
__global__ void __launch_bounds__(256) k_gemm1(const float* __restrict__ X,
                                               const float* __restrict__ W) {
    __shared__ __align__(16) float As[3][16][136];   // [stage][k][m]
    __shared__ __align__(16) float Bs[3][16][72];    // [stage][k][n]
    const int t    = threadIdx.x;
    const int warp = t >> 5;
    const int wm   = warp >> 1;
    const int wn   = warp & 1;
    const int block_row = blockIdx.x * 128;

    wmma::fragment<wmma::accumulator, 16, 16, 8, float> acc[2][2];
#pragma unroll
    for (int i = 0; i < 2; i++)
#pragma unroll
        for (int j = 0; j < 2; j++) wmma::fill_fragment(acc[i][j], 0.0f);

    const int ar = t >> 4;
    const int ak = t & 15;
    const int brow = t >> 4;
    const int bc4  = t & 15;

#pragma unroll
    for (int pt = 0; pt < 2; pt++) {
        const int k0 = pt * 16;
#pragma unroll
        for (int i = 0; i < 8; i++) {
            int r = ar + i * 16;
            int gr = block_row + r;
            cp_async4(&As[pt][ak][r], X + (size_t)gr * FIN + k0 + ak, gr < N_NODES);
        }
        cp_async16(&Bs[pt][brow][bc4 * 4], W + (k0 + brow) * HD + bc4 * 4, true);
        asm volatile("cp.async.commit_group;");
    }

    for (int kt = 0; kt < KT_TILES; kt++) {
        const int cur = kt % 3;
        if (kt + 2 < KT_TILES) {
            const int nk0 = (kt + 2) * 16;
            const int nxt = (kt + 2) % 3;
#pragma unroll
            for (int i = 0; i < 8; i++) {
                int r = ar + i * 16;
                int gr = block_row + r, gk = nk0 + ak;
                cp_async4(&As[nxt][ak][r], X + (size_t)gr * FIN + gk,
                          (gr < N_NODES) && (gk < FIN));
            }
            {
                int gk = nk0 + brow;
                cp_async16(&Bs[nxt][brow][bc4 * 4], W + gk * HD + bc4 * 4, gk < FIN);
            }
            asm volatile("cp.async.commit_group;");
            asm volatile("cp.async.wait_group 2;");
        } else {
            asm volatile("cp.async.wait_group 0;");
        }
        __syncthreads();

#pragma unroll
        for (int ks = 0; ks < 2; ks++) {
            wmma::fragment<wmma::matrix_a, 16, 16, 8, wmma::precision::tf32, wmma::col_major> af[2];
            wmma::fragment<wmma::matrix_b, 16, 16, 8, wmma::precision::tf32, wmma::row_major> bf[2];
#pragma unroll
            for (int i = 0; i < 2; i++)
                wmma::load_matrix_sync(af[i], &As[cur][ks * 8][wm * 32 + i * 16], 136);
#pragma unroll
            for (int j = 0; j < 2; j++)
                wmma::load_matrix_sync(bf[j], &Bs[cur][ks * 8][wn * 32 + j * 16], 72);
#pragma unroll
            for (int i = 0; i < 2; i++)
#pragma unroll
                for (int j = 0; j < 2; j++)
                    wmma::mma_sync(acc[i][j], af[i], bf[j], acc[i][j]);
        }
        __syncthreads();
    }

#pragma unroll
    for (int i = 0; i < 2; i++) {
        int row = block_row + wm * 32 + i * 16;
#pragma unroll
        for (int j = 0; j < 2; j++) {
            int col = wn * 32 + j * 16;
            wmma::store_matrix_sync(&g_bufA[row * HD + col], acc[i][j], HD, wmma::mem_row_major);
        }
    }
}

// ---------------- GCN propagation as gather (MLP=8 batched): bufB[i] = sum incoming -------
// warp per node; lane owns one float2 slice. Edges processed in predicated batches of 8
// so 8 independent feature loads are in flight (fixes the serial-latency bound of R15).
__global__ void __launch_bounds__(256) k_gather() {
    int w = (blockIdx.x * blockDim.x + threadIdx.x) >> 5;
    int lane = threadIdx.x & 31;
    if (w >= N_NODES) return;
    float di = g_dinv[w];
    const float2* __restrict__ inp = (const float2*)g_bufA;
    float2 a = inp[w * 32 + lane];
    float s2 = di * di;
    float accx = a.x * s2, accy = a.y * s2;   // self-loop
    const int beg = g_ptr[w], end = g_ptr[w + 1];
    for (int idx = beg; idx < end; idx += 8) {
        int   s[8];
        float n[8];
#pragma unroll
        for (int j = 0; j < 8; j++) {
            bool p = (idx + j) < end;
            s[j] = p ? __ldg(&g_csrc[idx + j]) : w;   // clamp to safe row
            n[j] = p ? __ldg(&g_dinv[s[j]]) * di : 0.f;
        }
        float2 v[8];
#pragma unroll
        for (int j = 0; j < 8; j++) v[j] = inp[s[j] * 32 + lane];
#pragma unroll
        for (int j = 0; j < 8; j++) {
            accx += v[j].x * n[j];
            accy += v[j].y * n[j];
        }
    }
    ((float2*)g_bufB)[w * 32 + lane] = make_float2(accx, accy);
}

// ---------------- GEMM2: bufA = relu(bufB + b1) @ W2   (64x64) ----------------
__global__ void __launch_bounds__(256) k_gemm2(const float* __restrict__ bias,
                                               const float* __restrict__ W) {
    __shared__ float Ws[HD * HD];
    __shared__ float As2[16][HD];
    const int t = threadIdx.x;
    const int rows = blockIdx.x * 16;
#pragma unroll
    for (int i = 0; i < 16; i++) Ws[t + i * 256] = W[t + i * 256];
#pragma unroll
    for (int i = 0; i < 4; i++) {
        int idx = t + i * 256;
        int r = idx >> 6, c = idx & 63;
        int gr = rows + r;
        float v = 0.f;
        if (gr < N_NODES) v = fmaxf(g_bufB[gr * HD + c] + bias[c], 0.f);
        As2[r][c] = v;
    }
    __syncthreads();
    int r = t >> 4, cg = t & 15;
    float acc[4] = {0.f, 0.f, 0.f, 0.f};
#pragma unroll
    for (int k = 0; k < HD; k++) {
        float a = As2[r][k];
#pragma unroll
        for (int j = 0; j < 4; j++) acc[j] += a * Ws[k * HD + cg + 16 * j];
    }
    int gr = rows + r;
    if (gr < N_NODES) {
#pragma unroll
        for (int j = 0; j < 4; j++) g_bufA[gr * HD + cg + 16 * j] = acc[j];
    }
}

// ---------------- GAT transform: hg = relu(bufB + b2) @ Wg  (64x14) ----------------
__global__ void k_gat_transform(const float* __restrict__ bias, const float* __restrict__ Wg) {
    __shared__ float Ws[HD * OC];
    int t = threadIdx.x;
    for (int idx = t; idx < HD * OC; idx += blockDim.x) Ws[idx] = Wg[idx];
    __syncthreads();
    int node = (blockIdx.x * blockDim.x + t) >> 5;
    int lane = t & 31;
    if (node >= N_NODES) return;
    float f_lo = fmaxf(g_bufB[node * HD + lane]      + bias[lane],      0.f);
    float f_hi = fmaxf(g_bufB[node * HD + 32 + lane] + bias[32 + lane], 0.f);
    int c = lane < OC ? lane : 0;
    float acc = 0.f;
#pragma unroll
    for (int k = 0; k < 32; k++) {
        float a = __shfl_sync(0xffffffffu, f_lo, k);
        acc += a * Ws[k * OC + c];
    }
#pragma unroll
    for (int k = 0; k < 32; k++) {
        float a = __shfl_sync(0xffffffffu, f_hi, k);
        acc += a * Ws[(k + 32) * OC + c];
    }
    if (lane < OC) g_hg[node * OC + lane] = acc;
}

// ---------------- attention scalars ----------------
__global__ void k_node_att(const float* __restrict__ att_src, const float* __restrict__ att_dst) {
    int tid = blockIdx.x * blockDim.x + threadIdx.x;
    if (tid >= N_NODES * NH) return;
    int i = tid >> 1, h = tid & 1;
    const float* hrow = g_hg + i * OC + h * NC;
    float as = 0.f, ad = 0.f;
#pragma unroll
    for (int c = 0; c < NC; c++) {
        as += hrow[c] * att_src[h * NC + c];
        ad += hrow[c] * att_dst[h * NC + c];
    }
    g_as[tid] = as;
    g_ad[tid] = ad;
}

// ---------------- fused GAT gather: segment max + softmax + aggregate + log_softmax ----------
// warp per node; lanes stride over incoming edges (parallel loads within the warp).
__global__ void __launch_bounds__(256) k_gat_gather(const float* __restrict__ bg,
                                                    float* __restrict__ out) {
    int w = (blockIdx.x * blockDim.x + threadIdx.x) >> 5;
    int lane = threadIdx.x & 31;
    if (w >= N_NODES) return;
    const int beg = g_ptr[w], end = g_ptr[w + 1];
    const float ad0 = g_ad[w * 2], ad1 = g_ad[w * 2 + 1];
    const float es0 = lrelu(g_as[w * 2]     + ad0);   // self-loop e-values
    const float es1 = lrelu(g_as[w * 2 + 1] + ad1);

    // pass 1: segment max (self seeds every lane)
    float m0 = es0, m1 = es1;
    for (int idx = beg + lane; idx < end; idx += 32) {
        int s = g_csrc[idx];
        m0 = fmaxf(m0, lrelu(g_as[s * 2]     + ad0));
        m1 = fmaxf(m1, lrelu(g_as[s * 2 + 1] + ad1));
    }
#pragma unroll
    for (int off = 16; off > 0; off >>= 1) {
        m0 = fmaxf(m0, __shfl_xor_sync(0xffffffffu, m0, off));
        m1 = fmaxf(m1, __shfl_xor_sync(0xffffffffu, m1, off));
    }

    // pass 2: denominator + weighted feature accumulation
    float s0 = 0.f, s1 = 0.f;
    float num[OC];
#pragma unroll
    for (int c = 0; c < OC; c++) num[c] = 0.f;
    if (lane == 0) {   // self-loop contribution once
        float p0 = expf(es0 - m0), p1 = expf(es1 - m1);
        s0 = p0; s1 = p1;
        const float* hr = g_hg + w * OC;
#pragma unroll
        for (int c = 0; c < NC; c++)  num[c]      = p0 * hr[c];
#pragma unroll
        for (int c = 0; c < NC; c++)  num[NC + c] = p1 * hr[NC + c];
    }
    for (int idx = beg + lane; idx < end; idx += 32) {
        int s = g_csrc[idx];
        float p0 = expf(lrelu(g_as[s * 2]     + ad0) - m0);
        float p1 = expf(lrelu(g_as[s * 2 + 1] + ad1) - m1);
        s0 += p0; s1 += p1;
        const float* hr = g_hg + s * OC;
#pragma unroll
        for (int c = 0; c < NC; c++)  num[c]      += p0 * hr[c];
#pragma unroll
        for (int c = 0; c < NC; c++)  num[NC + c] += p1 * hr[NC + c];
    }
#pragma unroll
    for (int off = 16; off > 0; off >>= 1) {
        s0 += __shfl_xor_sync(0xffffffffu, s0, off);
        s1 += __shfl_xor_sync(0xffffffffu, s1, off);
#pragma unroll
        for (int c = 0; c < OC; c++)
            num[c] += __shfl_xor_sync(0xffffffffu, num[c], off);
    }

    // logits held one-per-lane (lanes 0..13), then warp log_softmax
    float v = -1e30f;
    if (lane < OC) {
        float denom = (lane < NC ? s0 : s1) + 1e-16f;
        v = num[lane] / denom + bg[lane];
    }
    float mx = v;
#pragma unroll
    for (int off = 16; off > 0; off >>= 1)
        mx = fmaxf(mx, __shfl_xor_sync(0xffffffffu, mx, off));
    float ex = (lane < OC) ? expf(v - mx) : 0.f;
    float se = ex;
#pragma unroll
    for (int off = 16; off > 0; off >>= 1)
        se += __shfl_xor_sync(0xffffffffu, se, off);
    float lse = mx + logf(se);
    if (lane < OC) out[w * OC + lane] = v - lse;
}

// ---------------- launch ----------------
extern "C" void kernel_launch(void* const* d_in, const int* in_sizes, int n_in,
                              void* d_out, int out_size) {
    const float* x       = (const float*)d_in[0];
    const int*   ei      = (const int*)  d_in[1];
    const float* W1      = (const float*)d_in[2];
    const float* b1      = (const float*)d_in[3];
    const float* W2      = (const float*)d_in[4];
    const float* b2      = (const float*)d_in[5];
    const float* Wg      = (const float*)d_in[6];
    const float* att_src = (const float*)d_in[7];
    const float* att_dst = (const float*)d_in[8];
    const float* bg      = (const float*)d_in[9];
    float* out = (float*)d_out;

    const int* src = ei;
    const int* dst = ei + NE;

    const int T = 256;
    // CSR build + normalization
    k_zero_cnt<<<(N_NODES + T - 1) / T, T>>>();
    k_count<<<(NE + T - 1) / T, T>>>(dst);
    k_dinv<<<(N_NODES + T - 1) / T, T>>>();
    k_scan1<<<SCAN_B, SCAN_T>>>();
    k_scan2<<<1, 32>>>();
    k_scan3<<<(N_NODES + T - 1) / T, T>>>();
    k_fill<<<(NE + T - 1) / T, T>>>(src, dst);

    // layer 1: transform (tensor cores + cp.async), gather
    k_gemm1<<<(N_NODES + 127) / 128, 256>>>(x, W1);
    k_gather<<<(N_NODES * 32 + T - 1) / T, T>>>();

    // layer 2: relu(agg+b1) @ W2, gather
    k_gemm2<<<(N_NODES + 15) / 16, 256>>>(b1, W2);
    k_gather<<<(N_NODES * 32 + T - 1) / T, T>>>();

    // GAT head (fused)
    k_gat_transform<<<(N_NODES * 32 + T - 1) / T, T>>>(b2, Wg);
    k_node_att<<<(N_NODES * NH + T - 1) / T, T>>>(att_src, att_dst);
    k_gat_gather<<<(N_NODES * 32 + T - 1) / T, T>>>(bg, out);
}